// round 4
// baseline (speedup 1.0000x reference)
#include <cuda_runtime.h>
#include <math.h>

#define C_   32
#define C2_  16
#define D_   48
#define H_   128
#define W_   160
#define HW_  (H_*W_)
#define NV_  4

// padded volume dims: (c2, D+2, H+2, Wp)
#define DP_  50
#define HP_  130
#define WP_  168
#define CSTRIDE_ (DP_*HP_*WP_)          // 1,092,000 u64 per c2
#define BORDER_PER_C2_ 108960           // padded cells - interior cells

typedef unsigned long long u64;

// Scratch (device globals: allocation-free rule)
__device__ float  g_rt[NV_][12];
__device__ float2 g_src2[NV_*C2_*HW_];        // src feats channel-paired
__device__ float2 g_ref2[NV_*C2_*HW_];        // ref feats channel-paired
__device__ u64    g_volp[C2_*CSTRIDE_];       // padded volume_mean, float2-as-u64
__device__ float  g_cost[D_*HW_];

// ---- packed f32x2 helpers (Blackwell) --------------------------------------
__device__ __forceinline__ u64 pk2(float a, float b) {
    u64 r; asm("mov.b64 %0,{%1,%2};" : "=l"(r) : "f"(a), "f"(b)); return r;
}
__device__ __forceinline__ void unpk2(u64 v, float& a, float& b) {
    asm("mov.b64 {%0,%1},%2;" : "=f"(a), "=f"(b) : "l"(v));
}
__device__ __forceinline__ u64 fma2_(u64 a, u64 b, u64 c) {
    u64 d; asm("fma.rn.f32x2 %0,%1,%2,%3;" : "=l"(d) : "l"(a), "l"(b), "l"(c)); return d;
}
__device__ __forceinline__ u64 mul2_(u64 a, u64 b) {
    u64 d; asm("mul.rn.f32x2 %0,%1,%2;" : "=l"(d) : "l"(a), "l"(b)); return d;
}

// ---------------------------------------------------------------------------
// K0: projection algebra (fp64). proj layout: (B=1, V=5, 2, 4, 4).
// ---------------------------------------------------------------------------
__global__ void k_params(const float* __restrict__ proj) {
    if (threadIdx.x != 0 || blockIdx.x != 0) return;

    double Ar[9], ar[3];
    {
        const float* E = proj;
        const float* K = proj + 16;
        for (int i = 0; i < 3; i++) {
            for (int j = 0; j < 3; j++) {
                double s = 0.0;
                for (int k = 0; k < 3; k++) s += (double)K[i*4+k] * (double)E[k*4+j];
                Ar[i*3+j] = s;
            }
            double s = 0.0;
            for (int k = 0; k < 3; k++) s += (double)K[i*4+k] * (double)E[k*4+3];
            ar[i] = s;
        }
    }
    double inv[9];
    double det = Ar[0]*(Ar[4]*Ar[8]-Ar[5]*Ar[7])
               - Ar[1]*(Ar[3]*Ar[8]-Ar[5]*Ar[6])
               + Ar[2]*(Ar[3]*Ar[7]-Ar[4]*Ar[6]);
    double id = 1.0 / det;
    inv[0] = (Ar[4]*Ar[8]-Ar[5]*Ar[7])*id;
    inv[1] = (Ar[2]*Ar[7]-Ar[1]*Ar[8])*id;
    inv[2] = (Ar[1]*Ar[5]-Ar[2]*Ar[4])*id;
    inv[3] = (Ar[5]*Ar[6]-Ar[3]*Ar[8])*id;
    inv[4] = (Ar[0]*Ar[8]-Ar[2]*Ar[6])*id;
    inv[5] = (Ar[2]*Ar[3]-Ar[0]*Ar[5])*id;
    inv[6] = (Ar[3]*Ar[7]-Ar[4]*Ar[6])*id;
    inv[7] = (Ar[1]*Ar[6]-Ar[0]*Ar[7])*id;
    inv[8] = (Ar[0]*Ar[4]-Ar[1]*Ar[3])*id;

    for (int v = 0; v < NV_; v++) {
        const float* E = proj + (v+1)*32;
        const float* K = proj + (v+1)*32 + 16;
        double As[9], as_[3];
        for (int i = 0; i < 3; i++) {
            for (int j = 0; j < 3; j++) {
                double s = 0.0;
                for (int k = 0; k < 3; k++) s += (double)K[i*4+k] * (double)E[k*4+j];
                As[i*3+j] = s;
            }
            double s = 0.0;
            for (int k = 0; k < 3; k++) s += (double)K[i*4+k] * (double)E[k*4+3];
            as_[i] = s;
        }
        double rot[9], tr[3];
        for (int i = 0; i < 3; i++)
            for (int j = 0; j < 3; j++) {
                double s = 0.0;
                for (int k = 0; k < 3; k++) s += As[i*3+k] * inv[k*3+j];
                rot[i*3+j] = s;
            }
        for (int i = 0; i < 3; i++) {
            double s = as_[i];
            for (int k = 0; k < 3; k++) s -= rot[i*3+k] * ar[k];
            tr[i] = s;
        }
        for (int i = 0; i < 9; i++) g_rt[v][i] = (float)rot[i];
        for (int i = 0; i < 3; i++) g_rt[v][9+i] = (float)tr[i];
    }
}

// ---------------------------------------------------------------------------
// Kc: (V,C,H,W) fp32 -> channel-paired float2. Exact permutation.
// ---------------------------------------------------------------------------
__global__ void __launch_bounds__(256) k_cvt(const float* __restrict__ src,
                                             const float* __restrict__ ref) {
    int idx = blockIdx.x * 256 + threadIdx.x;
    if (idx >= NV_*C2_*HW_) return;
    int p   = idx % HW_;
    int vc2 = idx / HW_;
    int v   = vc2 >> 4;
    int c2  = vc2 & 15;
    size_t a = (size_t)(v*C_ + 2*c2) * HW_ + p;
    g_src2[idx] = make_float2(src[a], src[a + HW_]);
    g_ref2[idx] = make_float2(ref[a], ref[a + HW_]);
}

// ---------------------------------------------------------------------------
// Kz: zero the padding border of g_volp (interior written by k_vol).
// ---------------------------------------------------------------------------
__global__ void __launch_bounds__(256) k_zero() {
    int idx = blockIdx.x * 256 + threadIdx.x;
    if (idx >= C2_*BORDER_PER_C2_) return;
    int c2 = idx / BORDER_PER_C2_;
    int t  = idx % BORDER_PER_C2_;
    int dd, yy, xx;
    if (t < 2*HP_*WP_) {                       // d = 0 / 49 full slabs
        int sl = t / (HP_*WP_);
        int rr = t % (HP_*WP_);
        dd = sl * (DP_-1);
        yy = rr / WP_;
        xx = rr % WP_;
    } else {
        int r = t - 2*HP_*WP_;
        dd = r / 1360 + 1;                     // per-d border = 2*168 + 128*8
        int s = r % 1360;
        if (s < 2*WP_) {                       // y = 0 / 129 rows
            yy = (s / WP_) * (HP_-1);
            xx = s % WP_;
        } else {
            int q = s - 2*WP_;
            yy = (q >> 3) + 1;
            int xc = q & 7;
            xx = (xc == 0) ? 0 : (W_ + xc);    // x=0 and x=161..167
        }
    }
    g_volp[(size_t)c2*CSTRIDE_ + ((size_t)dd*HP_ + yy)*WP_ + xx] = 0ULL;
}

// ---------------------------------------------------------------------------
// K1: build volume_mean into padded layout. Block = 32 x-pixels x 1 y x 48 d.
// rot·(x,y,1) hoisted out of d loop; packed f32x2 tap blending.
// ---------------------------------------------------------------------------
__global__ void __launch_bounds__(256) k_vol(const float* __restrict__ depv) {
    __shared__ u64 refs[NV_*C2_*32];

    const int tx = threadIdx.x;
    const int dg = threadIdx.y;
    const int tid = dg*32 + tx;
    const int x0 = blockIdx.x * 32;
    const int y  = blockIdx.y;
    const int x  = x0 + tx;

    for (int i = tid; i < NV_*C2_*32; i += 256) {
        int v  = i >> 9;
        int r  = i & 511;
        int c2 = r >> 5;
        int xx = r & 31;
        refs[i] = ((const u64*)g_ref2)[(v*C2_ + c2)*HW_ + y*W_ + x0 + xx];
    }
    __syncthreads();

    const float fx = (float)x, fy = (float)y;
    float hx[NV_], hy[NV_], hz[NV_];
#pragma unroll
    for (int v = 0; v < NV_; v++) {
        const float* rt = g_rt[v];
        hx[v] = rt[0]*fx + rt[1]*fy + rt[2];
        hy[v] = rt[3]*fx + rt[4]*fy + rt[5];
        hz[v] = rt[6]*fx + rt[7]*fy + rt[8];
    }

    for (int i = 0; i < 6; i++) {
        const int d = dg*6 + i;
        const float dep = depv[d];

        int off[NV_][4];
        u64 w2[NV_][4];
#pragma unroll
        for (int v = 0; v < NV_; v++) {
            const float* rt = g_rt[v];
            float pz  = hz[v]*dep + rt[11];
            float ipz = 1.0f / pz;
            float px  = (hx[v]*dep + rt[9])  * ipz;
            float py  = (hy[v]*dep + rt[10]) * ipz;

            float x0f = floorf(px), y0f = floorf(py);
            float wx = px - x0f,    wy = py - y0f;

            bool vx0 = (x0f >=  0.f) && (x0f <= (float)(W_-1));
            bool vx1 = (x0f >= -1.f) && (x0f <= (float)(W_-2));
            bool vy0 = (y0f >=  0.f) && (y0f <= (float)(H_-1));
            bool vy1 = (y0f >= -1.f) && (y0f <= (float)(H_-2));

            int ix0 = min(max((int)x0f,     0), W_-1);
            int ix1 = min(max((int)x0f + 1, 0), W_-1);
            int iy0 = min(max((int)y0f,     0), H_-1);
            int iy1 = min(max((int)y0f + 1, 0), H_-1);

            float w0 = (vx0 && vy0) ? (1.f-wx)*(1.f-wy) : 0.f;
            float w1 = (vx1 && vy0) ? wx*(1.f-wy)       : 0.f;
            float w2s= (vx0 && vy1) ? (1.f-wx)*wy       : 0.f;
            float w3 = (vx1 && vy1) ? wx*wy             : 0.f;

            w2[v][0] = pk2(w0, w0);
            w2[v][1] = pk2(w1, w1);
            w2[v][2] = pk2(w2s, w2s);
            w2[v][3] = pk2(w3, w3);

            off[v][0] = iy0*W_ + ix0;
            off[v][1] = iy0*W_ + ix1;
            off[v][2] = iy1*W_ + ix0;
            off[v][3] = iy1*W_ + ix1;
        }

        const u64 quart = pk2(0.25f, 0.25f);
        u64* dst = g_volp + ((size_t)(d+1)*HP_ + (y+1))*WP_ + (x+1);

#pragma unroll 4
        for (int c2 = 0; c2 < C2_; c2++) {
            u64 a2 = 0ULL;
#pragma unroll
            for (int v = 0; v < NV_; v++) {
                const u64* S = (const u64*)g_src2 + (size_t)(v*C2_ + c2) * HW_;
                u64 t0 = __ldg(S + off[v][0]);
                u64 t1 = __ldg(S + off[v][1]);
                u64 t2 = __ldg(S + off[v][2]);
                u64 t3 = __ldg(S + off[v][3]);
                u64 s2 = mul2_(w2[v][0], t0);
                s2 = fma2_(w2[v][1], t1, s2);
                s2 = fma2_(w2[v][2], t2, s2);
                s2 = fma2_(w2[v][3], t3, s2);
                a2 = fma2_(refs[(v*C2_ + c2)*32 + tx], s2, a2);
            }
            dst[(size_t)c2*CSTRIDE_] = mul2_(a2, quart);
        }
    }
}

// ---------------------------------------------------------------------------
// K2: 3x3x3 conv via padded volume. No bounds checks, no div/mod in hot loop,
// packed f32x2 FMA (channel pairs). Thread owns 8 d-outputs.
// ---------------------------------------------------------------------------
__global__ void __launch_bounds__(256) k_conv(const float* __restrict__ wreg) {
    __shared__ u64 tile[3400];           // [10 d][10 y][34 x]
    __shared__ u64 wsh2[C2_*27];         // packed (even,odd) channel weights

    const int tx = threadIdx.x, ty = threadIdx.y;
    const int tid = ty*32 + tx;
    const int x0 = blockIdx.x*32, y0 = blockIdx.y*8, d0 = blockIdx.z*8;

    for (int i = tid; i < C2_*27; i += 256) {
        int c2 = i / 27, t = i % 27;
        wsh2[i] = pk2(wreg[(2*c2)*27 + t], wreg[(2*c2+1)*27 + t]);
    }

    // precompute tile-load offsets (14 per thread; last partial)
    int gOff[14];
#pragma unroll
    for (int k = 0; k < 14; k++) {
        int i = tid + k*256;
        if (i < 3400) {
            int dd = i / 340;
            int r  = i - dd*340;
            int yy = r / 34;
            int xx = r - yy*34;
            gOff[k] = (dd*HP_ + yy)*WP_ + xx;
        } else gOff[k] = 0;
    }
    const size_t base0 = ((size_t)d0*HP_ + y0)*WP_ + x0;

    u64 acc2[8];
#pragma unroll
    for (int j = 0; j < 8; j++) acc2[j] = 0ULL;

    for (int c2 = 0; c2 < C2_; c2++) {
        __syncthreads();
        const u64* p = g_volp + (size_t)c2*CSTRIDE_ + base0;
#pragma unroll
        for (int k = 0; k < 13; k++)
            tile[tid + k*256] = __ldg(p + gOff[k]);
        if (tid < 3400 - 13*256)
            tile[tid + 13*256] = __ldg(p + gOff[13]);
        __syncthreads();

#pragma unroll
        for (int dy = 0; dy < 3; dy++)
#pragma unroll
        for (int dx = 0; dx < 3; dx++) {
            u64 col[10];
#pragma unroll
            for (int k = 0; k < 10; k++)
                col[k] = tile[k*340 + (ty + dy)*34 + tx + dx];
#pragma unroll
            for (int dz = 0; dz < 3; dz++) {
                u64 w = wsh2[c2*27 + dz*9 + dy*3 + dx];
#pragma unroll
                for (int j = 0; j < 8; j++)
                    acc2[j] = fma2_(w, col[j + dz], acc2[j]);
            }
        }
    }

#pragma unroll
    for (int j = 0; j < 8; j++) {
        float a, b;
        unpk2(acc2[j], a, b);
        g_cost[(size_t)(d0 + j)*HW_ + (y0 + ty)*W_ + (x0 + tx)] = a + b;
    }
}

// ---------------------------------------------------------------------------
// K3: softmax over D + expected depth + confidence. Cost cached in registers.
// ---------------------------------------------------------------------------
__global__ void __launch_bounds__(W_) k_post(const float* __restrict__ depv,
                                             float* __restrict__ out) {
    const int x = threadIdx.x;
    const int y = blockIdx.x;
    const int pix = y*W_ + x;

    float cv[D_];
    float m = -1e30f;
#pragma unroll
    for (int d = 0; d < D_; d++) {
        cv[d] = g_cost[(size_t)d*HW_ + pix];
        m = fmaxf(m, cv[d]);
    }

    float s = 0.f, sd = 0.f, sdep = 0.f;
#pragma unroll
    for (int d = 0; d < D_; d++) {
        float e = expf(cv[d] - m);
        s    += e;
        sd   += e * (float)d;
        sdep += e * depv[d];
    }
    float invs = 1.f / s;
    out[pix] = sdep * invs;

    int idx = (int)(sd * invs);
    idx = min(max(idx, 0), D_-1);

    float cw = 0.f;
#pragma unroll
    for (int t = -1; t <= 2; t++) {
        int dd = idx + t;
        if (dd >= 0 && dd < D_)
            cw += expf(cv[dd] - m);
    }
    out[HW_ + pix] = cw * invs;
}

// ---------------------------------------------------------------------------
extern "C" void kernel_launch(void* const* d_in, const int* in_sizes, int n_in,
                              void* d_out, int out_size) {
    const float* ref  = (const float*)d_in[0];
    const float* src  = (const float*)d_in[1];
    const float* proj = (const float*)d_in[2];
    const float* depv = (const float*)d_in[3];

    const float* wreg = (const float*)d_in[n_in - 1];
    for (int i = 4; i < n_in; i++)
        if (in_sizes[i] == C_*27) { wreg = (const float*)d_in[i]; break; }

    float* out = (float*)d_out;

    k_params<<<1, 32>>>(proj);
    k_cvt<<<(NV_*C2_*HW_ + 255)/256, 256>>>(src, ref);
    k_zero<<<(C2_*BORDER_PER_C2_ + 255)/256, 256>>>();
    k_vol<<<dim3(W_/32, H_), dim3(32, 8)>>>(depv);
    k_conv<<<dim3(W_/32, H_/8, D_/8), dim3(32, 8)>>>(wreg);
    k_post<<<H_, W_>>>(depv, out);
}

// round 5
// speedup vs baseline: 1.3345x; 1.3345x over previous
#include <cuda_runtime.h>
#include <math.h>

#define C_   32
#define C2_  16
#define D_   48
#define H_   128
#define W_   160
#define HW_  (H_*W_)
#define NV_  4

// padded volume dims: (c2, D+2, H+2, Wp)
#define DP_  50
#define HP_  130
#define WP_  168
#define CSTRIDE_ (DP_*HP_*WP_)
#define BORDER_PER_C2_ 108960

// Scratch (device globals: allocation-free rule)
__device__ float  g_rt[NV_][12];
__device__ float2 g_src2[NV_*C2_*HW_];        // src feats channel-paired
__device__ float2 g_ref2[NV_*C2_*HW_];        // ref feats channel-paired
__device__ float2 g_volp[C2_*CSTRIDE_];       // padded volume_mean
__device__ float  g_cost[D_*HW_];

// ---------------------------------------------------------------------------
// K0: projection algebra (fp64). proj layout: (B=1, V=5, 2, 4, 4).
// ---------------------------------------------------------------------------
__global__ void k_params(const float* __restrict__ proj) {
    if (threadIdx.x != 0 || blockIdx.x != 0) return;

    double Ar[9], ar[3];
    {
        const float* E = proj;
        const float* K = proj + 16;
        for (int i = 0; i < 3; i++) {
            for (int j = 0; j < 3; j++) {
                double s = 0.0;
                for (int k = 0; k < 3; k++) s += (double)K[i*4+k] * (double)E[k*4+j];
                Ar[i*3+j] = s;
            }
            double s = 0.0;
            for (int k = 0; k < 3; k++) s += (double)K[i*4+k] * (double)E[k*4+3];
            ar[i] = s;
        }
    }
    double inv[9];
    double det = Ar[0]*(Ar[4]*Ar[8]-Ar[5]*Ar[7])
               - Ar[1]*(Ar[3]*Ar[8]-Ar[5]*Ar[6])
               + Ar[2]*(Ar[3]*Ar[7]-Ar[4]*Ar[6]);
    double id = 1.0 / det;
    inv[0] = (Ar[4]*Ar[8]-Ar[5]*Ar[7])*id;
    inv[1] = (Ar[2]*Ar[7]-Ar[1]*Ar[8])*id;
    inv[2] = (Ar[1]*Ar[5]-Ar[2]*Ar[4])*id;
    inv[3] = (Ar[5]*Ar[6]-Ar[3]*Ar[8])*id;
    inv[4] = (Ar[0]*Ar[8]-Ar[2]*Ar[6])*id;
    inv[5] = (Ar[2]*Ar[3]-Ar[0]*Ar[5])*id;
    inv[6] = (Ar[3]*Ar[7]-Ar[4]*Ar[6])*id;
    inv[7] = (Ar[1]*Ar[6]-Ar[0]*Ar[7])*id;
    inv[8] = (Ar[0]*Ar[4]-Ar[1]*Ar[3])*id;

    for (int v = 0; v < NV_; v++) {
        const float* E = proj + (v+1)*32;
        const float* K = proj + (v+1)*32 + 16;
        double As[9], as_[3];
        for (int i = 0; i < 3; i++) {
            for (int j = 0; j < 3; j++) {
                double s = 0.0;
                for (int k = 0; k < 3; k++) s += (double)K[i*4+k] * (double)E[k*4+j];
                As[i*3+j] = s;
            }
            double s = 0.0;
            for (int k = 0; k < 3; k++) s += (double)K[i*4+k] * (double)E[k*4+3];
            as_[i] = s;
        }
        double rot[9], tr[3];
        for (int i = 0; i < 3; i++)
            for (int j = 0; j < 3; j++) {
                double s = 0.0;
                for (int k = 0; k < 3; k++) s += As[i*3+k] * inv[k*3+j];
                rot[i*3+j] = s;
            }
        for (int i = 0; i < 3; i++) {
            double s = as_[i];
            for (int k = 0; k < 3; k++) s -= rot[i*3+k] * ar[k];
            tr[i] = s;
        }
        for (int i = 0; i < 9; i++) g_rt[v][i] = (float)rot[i];
        for (int i = 0; i < 3; i++) g_rt[v][9+i] = (float)tr[i];
    }
}

// ---------------------------------------------------------------------------
// Kc: (V,C,H,W) fp32 -> channel-paired float2. Exact permutation.
// ---------------------------------------------------------------------------
__global__ void __launch_bounds__(256) k_cvt(const float* __restrict__ src,
                                             const float* __restrict__ ref) {
    int idx = blockIdx.x * 256 + threadIdx.x;
    if (idx >= NV_*C2_*HW_) return;
    int p   = idx % HW_;
    int vc2 = idx / HW_;
    int v   = vc2 >> 4;
    int c2  = vc2 & 15;
    size_t a = (size_t)(v*C_ + 2*c2) * HW_ + p;
    g_src2[idx] = make_float2(src[a], src[a + HW_]);
    g_ref2[idx] = make_float2(ref[a], ref[a + HW_]);
}

// ---------------------------------------------------------------------------
// Kz: zero the padding border of g_volp (interior written by k_vol).
// ---------------------------------------------------------------------------
__global__ void __launch_bounds__(256) k_zero() {
    int idx = blockIdx.x * 256 + threadIdx.x;
    if (idx >= C2_*BORDER_PER_C2_) return;
    int c2 = idx / BORDER_PER_C2_;
    int t  = idx % BORDER_PER_C2_;
    int dd, yy, xx;
    if (t < 2*HP_*WP_) {                       // d = 0 / 49 full slabs
        int sl = t / (HP_*WP_);
        int rr = t % (HP_*WP_);
        dd = sl * (DP_-1);
        yy = rr / WP_;
        xx = rr % WP_;
    } else {
        int r = t - 2*HP_*WP_;
        dd = r / 1360 + 1;                     // per-d border = 2*168 + 128*8
        int s = r % 1360;
        if (s < 2*WP_) {                       // y = 0 / 129 rows
            yy = (s / WP_) * (HP_-1);
            xx = s % WP_;
        } else {
            int q = s - 2*WP_;
            yy = (q >> 3) + 1;
            int xc = q & 7;
            xx = (xc == 0) ? 0 : (W_ + xc);    // x=0 and x=161..167
        }
    }
    g_volp[(size_t)c2*CSTRIDE_ + ((size_t)dd*HP_ + yy)*WP_ + xx] = make_float2(0.f, 0.f);
}

// ---------------------------------------------------------------------------
// K1: build volume_mean (padded layout). Block = 32 x-pixels x 1 y x 48 d.
// Scalar float2 math (register-lean, latency-bound kernel -> occupancy first).
// ---------------------------------------------------------------------------
__global__ void __launch_bounds__(256) k_vol(const float* __restrict__ depv) {
    __shared__ float2 refs[NV_][C2_][32];

    const int tx = threadIdx.x;
    const int dg = threadIdx.y;
    const int tid = dg*32 + tx;
    const int x0 = blockIdx.x * 32;
    const int y  = blockIdx.y;
    const int x  = x0 + tx;

    for (int i = tid; i < NV_*C2_*32; i += 256) {
        int v  = i >> 9;
        int r  = i & 511;
        int c2 = r >> 5;
        int xx = r & 31;
        refs[v][c2][xx] = g_ref2[(v*C2_ + c2)*HW_ + y*W_ + x0 + xx];
    }
    __syncthreads();

    const float fx = (float)x, fy = (float)y;
    float hx[NV_], hy[NV_], hz[NV_];
#pragma unroll
    for (int v = 0; v < NV_; v++) {
        const float* rt = g_rt[v];
        hx[v] = rt[0]*fx + rt[1]*fy + rt[2];
        hy[v] = rt[3]*fx + rt[4]*fy + rt[5];
        hz[v] = rt[6]*fx + rt[7]*fy + rt[8];
    }

    for (int i = 0; i < 6; i++) {
        const int d = dg*6 + i;
        const float dep = depv[d];

        int   off[NV_][4];
        float wgt[NV_][4];
#pragma unroll
        for (int v = 0; v < NV_; v++) {
            const float* rt = g_rt[v];
            float pz  = hz[v]*dep + rt[11];
            float ipz = 1.0f / pz;
            float px  = (hx[v]*dep + rt[9])  * ipz;
            float py  = (hy[v]*dep + rt[10]) * ipz;

            float x0f = floorf(px), y0f = floorf(py);
            float wx = px - x0f,    wy = py - y0f;

            bool vx0 = (x0f >=  0.f) && (x0f <= (float)(W_-1));
            bool vx1 = (x0f >= -1.f) && (x0f <= (float)(W_-2));
            bool vy0 = (y0f >=  0.f) && (y0f <= (float)(H_-1));
            bool vy1 = (y0f >= -1.f) && (y0f <= (float)(H_-2));

            int ix0 = min(max((int)x0f,     0), W_-1);
            int ix1 = min(max((int)x0f + 1, 0), W_-1);
            int iy0 = min(max((int)y0f,     0), H_-1);
            int iy1 = min(max((int)y0f + 1, 0), H_-1);

            wgt[v][0] = (vx0 && vy0) ? (1.f-wx)*(1.f-wy) : 0.f;
            wgt[v][1] = (vx1 && vy0) ? wx*(1.f-wy)       : 0.f;
            wgt[v][2] = (vx0 && vy1) ? (1.f-wx)*wy       : 0.f;
            wgt[v][3] = (vx1 && vy1) ? wx*wy             : 0.f;

            off[v][0] = iy0*W_ + ix0;
            off[v][1] = iy0*W_ + ix1;
            off[v][2] = iy1*W_ + ix0;
            off[v][3] = iy1*W_ + ix1;
        }

        float2* dst = g_volp + ((size_t)(d+1)*HP_ + (y+1))*WP_ + (x+1);

#pragma unroll 4
        for (int c2 = 0; c2 < C2_; c2++) {
            float ax = 0.f, ay = 0.f;
#pragma unroll
            for (int v = 0; v < NV_; v++) {
                const float2* S = g_src2 + (size_t)(v*C2_ + c2) * HW_;
                float2 t0 = __ldg(&S[off[v][0]]);
                float2 t1 = __ldg(&S[off[v][1]]);
                float2 t2 = __ldg(&S[off[v][2]]);
                float2 t3 = __ldg(&S[off[v][3]]);
                float sx = wgt[v][0]*t0.x + wgt[v][1]*t1.x + wgt[v][2]*t2.x + wgt[v][3]*t3.x;
                float sy = wgt[v][0]*t0.y + wgt[v][1]*t1.y + wgt[v][2]*t2.y + wgt[v][3]*t3.y;
                float2 r = refs[v][c2][tx];
                ax += r.x * sx;
                ay += r.y * sy;
            }
            dst[(size_t)c2*CSTRIDE_] = make_float2(ax*0.25f, ay*0.25f);
        }
    }
}

// ---------------------------------------------------------------------------
// K2: 3x3x3 conv via padded volume. No bounds checks, no div/mod in hot loop.
// Scalar float2 FMA. Thread owns 8 d-outputs (register sliding window).
// ---------------------------------------------------------------------------
__global__ void __launch_bounds__(256) k_conv(const float* __restrict__ wreg) {
    __shared__ float2 tile[3400];        // [10 d][10 y][34 x]
    __shared__ float2 wsh2[C2_*27];      // (even,odd) channel weights

    const int tx = threadIdx.x, ty = threadIdx.y;
    const int tid = ty*32 + tx;
    const int x0 = blockIdx.x*32, y0 = blockIdx.y*8, d0 = blockIdx.z*8;

    for (int i = tid; i < C2_*27; i += 256) {
        int c2 = i / 27, t = i % 27;
        wsh2[i] = make_float2(wreg[(2*c2)*27 + t], wreg[(2*c2+1)*27 + t]);
    }

    // precompute tile-load gmem offsets (14 per thread; last partial)
    int gOff[14];
#pragma unroll
    for (int k = 0; k < 14; k++) {
        int i = tid + k*256;
        if (i < 3400) {
            int dd = i / 340;
            int r  = i - dd*340;
            int yy = r / 34;
            int xx = r - yy*34;
            gOff[k] = (dd*HP_ + yy)*WP_ + xx;
        } else gOff[k] = 0;
    }
    const size_t base0 = ((size_t)d0*HP_ + y0)*WP_ + x0;

    float accx[8], accy[8];
#pragma unroll
    for (int j = 0; j < 8; j++) { accx[j] = 0.f; accy[j] = 0.f; }

    for (int c2 = 0; c2 < C2_; c2++) {
        __syncthreads();
        const float2* p = g_volp + (size_t)c2*CSTRIDE_ + base0;
#pragma unroll
        for (int k = 0; k < 13; k++)
            tile[tid + k*256] = __ldg(p + gOff[k]);
        if (tid < 3400 - 13*256)
            tile[tid + 13*256] = __ldg(p + gOff[13]);
        __syncthreads();

#pragma unroll
        for (int dy = 0; dy < 3; dy++)
#pragma unroll
        for (int dx = 0; dx < 3; dx++) {
            float2 col[10];
#pragma unroll
            for (int k = 0; k < 10; k++)
                col[k] = tile[k*340 + (ty + dy)*34 + tx + dx];
#pragma unroll
            for (int dz = 0; dz < 3; dz++) {
                float2 w = wsh2[c2*27 + dz*9 + dy*3 + dx];
#pragma unroll
                for (int j = 0; j < 8; j++) {
                    accx[j] += w.x * col[j + dz].x;
                    accy[j] += w.y * col[j + dz].y;
                }
            }
        }
    }

#pragma unroll
    for (int j = 0; j < 8; j++)
        g_cost[(size_t)(d0 + j)*HW_ + (y0 + ty)*W_ + (x0 + tx)] = accx[j] + accy[j];
}

// ---------------------------------------------------------------------------
// K3: softmax over D + expected depth + confidence. Cost cached in registers.
// ---------------------------------------------------------------------------
__global__ void __launch_bounds__(W_) k_post(const float* __restrict__ depv,
                                             float* __restrict__ out) {
    const int x = threadIdx.x;
    const int y = blockIdx.x;
    const int pix = y*W_ + x;

    float cv[D_];
    float m = -1e30f;
#pragma unroll
    for (int d = 0; d < D_; d++) {
        cv[d] = g_cost[(size_t)d*HW_ + pix];
        m = fmaxf(m, cv[d]);
    }

    float s = 0.f, sd = 0.f, sdep = 0.f;
#pragma unroll
    for (int d = 0; d < D_; d++) {
        float e = expf(cv[d] - m);
        s    += e;
        sd   += e * (float)d;
        sdep += e * depv[d];
    }
    float invs = 1.f / s;
    out[pix] = sdep * invs;

    int idx = (int)(sd * invs);
    idx = min(max(idx, 0), D_-1);

    float cw = 0.f;
#pragma unroll
    for (int t = -1; t <= 2; t++) {
        int dd = idx + t;
        if (dd >= 0 && dd < D_)
            cw += expf(cv[dd] - m);
    }
    out[HW_ + pix] = cw * invs;
}

// ---------------------------------------------------------------------------
extern "C" void kernel_launch(void* const* d_in, const int* in_sizes, int n_in,
                              void* d_out, int out_size) {
    const float* ref  = (const float*)d_in[0];
    const float* src  = (const float*)d_in[1];
    const float* proj = (const float*)d_in[2];
    const float* depv = (const float*)d_in[3];

    const float* wreg = (const float*)d_in[n_in - 1];
    for (int i = 4; i < n_in; i++)
        if (in_sizes[i] == C_*27) { wreg = (const float*)d_in[i]; break; }

    float* out = (float*)d_out;

    k_params<<<1, 32>>>(proj);
    k_cvt<<<(NV_*C2_*HW_ + 255)/256, 256>>>(src, ref);
    k_zero<<<(C2_*BORDER_PER_C2_ + 255)/256, 256>>>();
    k_vol<<<dim3(W_/32, H_), dim3(32, 8)>>>(depv);
    k_conv<<<dim3(W_/32, H_/8, D_/8), dim3(32, 8)>>>(wreg);
    k_post<<<H_, W_>>>(depv, out);
}

// round 6
// speedup vs baseline: 1.5846x; 1.1874x over previous
#include <cuda_runtime.h>
#include <math.h>

#define C_   32
#define C2_  16
#define D_   48
#define H_   128
#define W_   160
#define HW_  (H_*W_)
#define NV_  4

// padded volume dims: (c2, D+2, H+2, Wp)
#define DP_  50
#define HP_  130
#define WP_  168
#define CSTRIDE_ (DP_*HP_*WP_)
#define BORDER_PER_C2_ 108960

// Scratch (device globals: allocation-free rule)
__device__ float  g_rt[NV_][12];
__device__ float2 g_src2[NV_*C2_*HW_];        // src feats channel-paired
__device__ float2 g_ref2[NV_*C2_*HW_];        // ref feats channel-paired
__device__ float2 g_volp[C2_*CSTRIDE_];       // padded volume_mean
__device__ float  g_cost[D_*HW_];

// ---------------------------------------------------------------------------
// K0: projection algebra (fp64). proj layout: (B=1, V=5, 2, 4, 4).
// ---------------------------------------------------------------------------
__global__ void k_params(const float* __restrict__ proj) {
    if (threadIdx.x != 0 || blockIdx.x != 0) return;

    double Ar[9], ar[3];
    {
        const float* E = proj;
        const float* K = proj + 16;
        for (int i = 0; i < 3; i++) {
            for (int j = 0; j < 3; j++) {
                double s = 0.0;
                for (int k = 0; k < 3; k++) s += (double)K[i*4+k] * (double)E[k*4+j];
                Ar[i*3+j] = s;
            }
            double s = 0.0;
            for (int k = 0; k < 3; k++) s += (double)K[i*4+k] * (double)E[k*4+3];
            ar[i] = s;
        }
    }
    double inv[9];
    double det = Ar[0]*(Ar[4]*Ar[8]-Ar[5]*Ar[7])
               - Ar[1]*(Ar[3]*Ar[8]-Ar[5]*Ar[6])
               + Ar[2]*(Ar[3]*Ar[7]-Ar[4]*Ar[6]);
    double id = 1.0 / det;
    inv[0] = (Ar[4]*Ar[8]-Ar[5]*Ar[7])*id;
    inv[1] = (Ar[2]*Ar[7]-Ar[1]*Ar[8])*id;
    inv[2] = (Ar[1]*Ar[5]-Ar[2]*Ar[4])*id;
    inv[3] = (Ar[5]*Ar[6]-Ar[3]*Ar[8])*id;
    inv[4] = (Ar[0]*Ar[8]-Ar[2]*Ar[6])*id;
    inv[5] = (Ar[2]*Ar[3]-Ar[0]*Ar[5])*id;
    inv[6] = (Ar[3]*Ar[7]-Ar[4]*Ar[6])*id;
    inv[7] = (Ar[1]*Ar[6]-Ar[0]*Ar[7])*id;
    inv[8] = (Ar[0]*Ar[4]-Ar[1]*Ar[3])*id;

    for (int v = 0; v < NV_; v++) {
        const float* E = proj + (v+1)*32;
        const float* K = proj + (v+1)*32 + 16;
        double As[9], as_[3];
        for (int i = 0; i < 3; i++) {
            for (int j = 0; j < 3; j++) {
                double s = 0.0;
                for (int k = 0; k < 3; k++) s += (double)K[i*4+k] * (double)E[k*4+j];
                As[i*3+j] = s;
            }
            double s = 0.0;
            for (int k = 0; k < 3; k++) s += (double)K[i*4+k] * (double)E[k*4+3];
            as_[i] = s;
        }
        double rot[9], tr[3];
        for (int i = 0; i < 3; i++)
            for (int j = 0; j < 3; j++) {
                double s = 0.0;
                for (int k = 0; k < 3; k++) s += As[i*3+k] * inv[k*3+j];
                rot[i*3+j] = s;
            }
        for (int i = 0; i < 3; i++) {
            double s = as_[i];
            for (int k = 0; k < 3; k++) s -= rot[i*3+k] * ar[k];
            tr[i] = s;
        }
        for (int i = 0; i < 9; i++) g_rt[v][i] = (float)rot[i];
        for (int i = 0; i < 3; i++) g_rt[v][9+i] = (float)tr[i];
    }
}

// ---------------------------------------------------------------------------
// Kc: (V,C,H,W) fp32 -> channel-paired float2. Exact permutation.
// ---------------------------------------------------------------------------
__global__ void __launch_bounds__(256) k_cvt(const float* __restrict__ src,
                                             const float* __restrict__ ref) {
    int idx = blockIdx.x * 256 + threadIdx.x;
    if (idx >= NV_*C2_*HW_) return;
    int p   = idx % HW_;
    int vc2 = idx / HW_;
    int v   = vc2 >> 4;
    int c2  = vc2 & 15;
    size_t a = (size_t)(v*C_ + 2*c2) * HW_ + p;
    g_src2[idx] = make_float2(src[a], src[a + HW_]);
    g_ref2[idx] = make_float2(ref[a], ref[a + HW_]);
}

// ---------------------------------------------------------------------------
// Kz: zero the padding border of g_volp (interior written by k_vol).
// ---------------------------------------------------------------------------
__global__ void __launch_bounds__(256) k_zero() {
    int idx = blockIdx.x * 256 + threadIdx.x;
    if (idx >= C2_*BORDER_PER_C2_) return;
    int c2 = idx / BORDER_PER_C2_;
    int t  = idx % BORDER_PER_C2_;
    int dd, yy, xx;
    if (t < 2*HP_*WP_) {                       // d = 0 / 49 full slabs
        int sl = t / (HP_*WP_);
        int rr = t % (HP_*WP_);
        dd = sl * (DP_-1);
        yy = rr / WP_;
        xx = rr % WP_;
    } else {
        int r = t - 2*HP_*WP_;
        dd = r / 1360 + 1;                     // per-d border = 2*168 + 128*8
        int s = r % 1360;
        if (s < 2*WP_) {                       // y = 0 / 129 rows
            yy = (s / WP_) * (HP_-1);
            xx = s % WP_;
        } else {
            int q = s - 2*WP_;
            yy = (q >> 3) + 1;
            int xc = q & 7;
            xx = (xc == 0) ? 0 : (W_ + xc);    // x=0 and x=161..167
        }
    }
    g_volp[(size_t)c2*CSTRIDE_ + ((size_t)dd*HP_ + yy)*WP_ + xx] = make_float2(0.f, 0.f);
}

// ---------------------------------------------------------------------------
// K1: build volume_mean (padded layout). Block = 32 x-pixels x 1 y x 48 d.
// Register-lean: per-view tap state = base offset + dx + dyW + 4 axis-masked
// factored weights. Projection recomputed per d (FMA pipe is idle).
// launch_bounds(256,3) pins >=3 blocks/SM.
// ---------------------------------------------------------------------------
__global__ void __launch_bounds__(256, 3) k_vol(const float* __restrict__ depv) {
    __shared__ float2 refs[NV_][C2_][32];

    const int tx = threadIdx.x;
    const int dg = threadIdx.y;
    const int tid = dg*32 + tx;
    const int x0 = blockIdx.x * 32;
    const int y  = blockIdx.y;
    const int x  = x0 + tx;

    for (int i = tid; i < NV_*C2_*32; i += 256) {
        int v  = i >> 9;
        int r  = i & 511;
        int c2 = r >> 5;
        int xx = r & 31;
        refs[v][c2][xx] = g_ref2[(v*C2_ + c2)*HW_ + y*W_ + x0 + xx];
    }
    __syncthreads();

    const float fx = (float)x, fy = (float)y;

    for (int i = 0; i < 6; i++) {
        const int d = dg*6 + i;
        const float dep = depv[d];

        int   base[NV_], dxo[NV_], dyo[NV_];
        float wx0[NV_], wx1[NV_], wy0[NV_], wy1[NV_];
#pragma unroll
        for (int v = 0; v < NV_; v++) {
            const float* rt = g_rt[v];
            float pz  = (rt[6]*fx + rt[7]*fy + rt[8])*dep + rt[11];
            float ipz = 1.0f / pz;
            float px  = ((rt[0]*fx + rt[1]*fy + rt[2])*dep + rt[9])  * ipz;
            float py  = ((rt[3]*fx + rt[4]*fy + rt[5])*dep + rt[10]) * ipz;

            float x0f = floorf(px), y0f = floorf(py);
            float wx = px - x0f,    wy = py - y0f;

            bool vx0 = (x0f >=  0.f) && (x0f <= (float)(W_-1));
            bool vx1 = (x0f >= -1.f) && (x0f <= (float)(W_-2));
            bool vy0 = (y0f >=  0.f) && (y0f <= (float)(H_-1));
            bool vy1 = (y0f >= -1.f) && (y0f <= (float)(H_-2));

            int ix0 = min(max((int)x0f,     0), W_-1);
            int ix1 = min(max((int)x0f + 1, 0), W_-1);
            int iy0 = min(max((int)y0f,     0), H_-1);
            int iy1 = min(max((int)y0f + 1, 0), H_-1);

            wx0[v] = vx0 ? (1.f - wx) : 0.f;
            wx1[v] = vx1 ? wx         : 0.f;
            wy0[v] = vy0 ? (1.f - wy) : 0.f;
            wy1[v] = vy1 ? wy         : 0.f;

            base[v] = iy0*W_ + ix0;
            dxo[v]  = ix1 - ix0;           // 0 or 1
            dyo[v]  = (iy1 - iy0)*W_;      // 0 or W_
        }

        float2* dst = g_volp + ((size_t)(d+1)*HP_ + (y+1))*WP_ + (x+1);

#pragma unroll 2
        for (int c2 = 0; c2 < C2_; c2++) {
            float ax = 0.f, ay = 0.f;
#pragma unroll
            for (int v = 0; v < NV_; v++) {
                const float2* S = g_src2 + (size_t)(v*C2_ + c2) * HW_;
                int o0 = base[v];
                int o1 = o0 + dxo[v];
                int o2 = o0 + dyo[v];
                int o3 = o2 + dxo[v];
                float2 t0 = __ldg(&S[o0]);
                float2 t1 = __ldg(&S[o1]);
                float2 t2 = __ldg(&S[o2]);
                float2 t3 = __ldg(&S[o3]);
                // factored bilinear with axis-masked weights
                float gx0 = wx0[v]*t0.x + wx1[v]*t1.x;
                float gx1 = wx0[v]*t2.x + wx1[v]*t3.x;
                float gy0 = wx0[v]*t0.y + wx1[v]*t1.y;
                float gy1 = wx0[v]*t2.y + wx1[v]*t3.y;
                float sx = wy0[v]*gx0 + wy1[v]*gx1;
                float sy = wy0[v]*gy0 + wy1[v]*gy1;
                float2 r = refs[v][c2][tx];
                ax += r.x * sx;
                ay += r.y * sy;
            }
            dst[(size_t)c2*CSTRIDE_] = make_float2(ax*0.25f, ay*0.25f);
        }
    }
}

// ---------------------------------------------------------------------------
// K2: 3x3x3 conv via padded volume, d-tile 4 (grid 960 -> ~80% occ).
// No bounds checks, no div/mod in hot loop. Thread owns 4 d-outputs.
// ---------------------------------------------------------------------------
__global__ void __launch_bounds__(256) k_conv(const float* __restrict__ wreg) {
    __shared__ float2 tile[2040];        // [6 d][10 y][34 x]
    __shared__ float2 wsh2[C2_*27];      // (even,odd) channel weights

    const int tx = threadIdx.x, ty = threadIdx.y;
    const int tid = ty*32 + tx;
    const int x0 = blockIdx.x*32, y0 = blockIdx.y*8, d0 = blockIdx.z*4;

    for (int i = tid; i < C2_*27; i += 256) {
        int c2 = i / 27, t = i % 27;
        wsh2[i] = make_float2(wreg[(2*c2)*27 + t], wreg[(2*c2+1)*27 + t]);
    }

    // precompute tile-load gmem offsets (8 per thread; last partial)
    int gOff[8];
#pragma unroll
    for (int k = 0; k < 8; k++) {
        int i = tid + k*256;
        if (i < 2040) {
            int dd = i / 340;
            int r  = i - dd*340;
            int yy = r / 34;
            int xx = r - yy*34;
            gOff[k] = (dd*HP_ + yy)*WP_ + xx;
        } else gOff[k] = 0;
    }
    const size_t base0 = ((size_t)d0*HP_ + y0)*WP_ + x0;

    float accx[4], accy[4];
#pragma unroll
    for (int j = 0; j < 4; j++) { accx[j] = 0.f; accy[j] = 0.f; }

    for (int c2 = 0; c2 < C2_; c2++) {
        __syncthreads();
        const float2* p = g_volp + (size_t)c2*CSTRIDE_ + base0;
#pragma unroll
        for (int k = 0; k < 7; k++)
            tile[tid + k*256] = __ldg(p + gOff[k]);
        if (tid < 2040 - 7*256)
            tile[tid + 7*256] = __ldg(p + gOff[7]);
        __syncthreads();

#pragma unroll
        for (int dy = 0; dy < 3; dy++)
#pragma unroll
        for (int dx = 0; dx < 3; dx++) {
            float2 col[6];
#pragma unroll
            for (int k = 0; k < 6; k++)
                col[k] = tile[k*340 + (ty + dy)*34 + tx + dx];
#pragma unroll
            for (int dz = 0; dz < 3; dz++) {
                float2 w = wsh2[c2*27 + dz*9 + dy*3 + dx];
#pragma unroll
                for (int j = 0; j < 4; j++) {
                    accx[j] += w.x * col[j + dz].x;
                    accy[j] += w.y * col[j + dz].y;
                }
            }
        }
    }

#pragma unroll
    for (int j = 0; j < 4; j++)
        g_cost[(size_t)(d0 + j)*HW_ + (y0 + ty)*W_ + (x0 + tx)] = accx[j] + accy[j];
}

// ---------------------------------------------------------------------------
// K3: softmax over D + expected depth + confidence. Cost cached in registers.
// ---------------------------------------------------------------------------
__global__ void __launch_bounds__(W_) k_post(const float* __restrict__ depv,
                                             float* __restrict__ out) {
    const int x = threadIdx.x;
    const int y = blockIdx.x;
    const int pix = y*W_ + x;

    float cv[D_];
    float m = -1e30f;
#pragma unroll
    for (int d = 0; d < D_; d++) {
        cv[d] = g_cost[(size_t)d*HW_ + pix];
        m = fmaxf(m, cv[d]);
    }

    float s = 0.f, sd = 0.f, sdep = 0.f;
#pragma unroll
    for (int d = 0; d < D_; d++) {
        float e = expf(cv[d] - m);
        s    += e;
        sd   += e * (float)d;
        sdep += e * depv[d];
    }
    float invs = 1.f / s;
    out[pix] = sdep * invs;

    int idx = (int)(sd * invs);
    idx = min(max(idx, 0), D_-1);

    float cw = 0.f;
#pragma unroll
    for (int t = -1; t <= 2; t++) {
        int dd = idx + t;
        if (dd >= 0 && dd < D_)
            cw += expf(cv[dd] - m);
    }
    out[HW_ + pix] = cw * invs;
}

// ---------------------------------------------------------------------------
extern "C" void kernel_launch(void* const* d_in, const int* in_sizes, int n_in,
                              void* d_out, int out_size) {
    const float* ref  = (const float*)d_in[0];
    const float* src  = (const float*)d_in[1];
    const float* proj = (const float*)d_in[2];
    const float* depv = (const float*)d_in[3];

    const float* wreg = (const float*)d_in[n_in - 1];
    for (int i = 4; i < n_in; i++)
        if (in_sizes[i] == C_*27) { wreg = (const float*)d_in[i]; break; }

    float* out = (float*)d_out;

    k_params<<<1, 32>>>(proj);
    k_cvt<<<(NV_*C2_*HW_ + 255)/256, 256>>>(src, ref);
    k_zero<<<(C2_*BORDER_PER_C2_ + 255)/256, 256>>>();
    k_vol<<<dim3(W_/32, H_), dim3(32, 8)>>>(depv);
    k_conv<<<dim3(W_/32, H_/8, D_/4), dim3(32, 8)>>>(wreg);
    k_post<<<H_, W_>>>(depv, out);
}